// round 12
// baseline (speedup 1.0000x reference)
#include <cuda_runtime.h>
#include <cuda_fp16.h>
#include <cstdint>

// ---------------------------------------------------------------------------
// FNO on sm_103a. Circulant Fourier layers via a 2KB reversed-g pair table:
// B[k][n] = g[(n-k-3) mod 256]. Uncropped circulant rows k=253..255 ARE the
// x-term coefficients, so x0..x2 live in h's k-columns 253..255 and the MMA
// computes conv + x-term together. True h[253..255] in a 1KB side array.
//   h0 = relu(mu @ W1 + b1)           (W1 via one-shot cp.async, ldsm path)
//   h  = relu(circ_g([h|x]) + h*lw)   l=0..3
//   out = h @ W2 + b2                 (fused into stage-4 epilogue, fp32)
// R12: h double-buffered (W1 image overlays h1) -> ONE barrier per Fourier
// stage; epilogue starts right after own MMAs, warps/CTAs desync.
// 256 threads, 64 rows/CTA, 85KB SMEM -> 2 CTAs/SM. No weight streaming.
// ---------------------------------------------------------------------------

#define NMODES 256
#define NLAYERS 4
#define MROWS 64
#define NTHREADS 256
#define HW 132                              // h row stride in 32-bit words
#define H_BYTES (MROWS * HW * 4)            // 33792
#define H0_OFF  0
#define H1_OFF  H_BYTES                     // W1 image overlays this (32768<=33792)
#define T2_OFF  (H1_OFF + H_BYTES)          // 67584: 4 x 2048B pair tables
#define LW_OFF  (T2_OFF + NLAYERS * 2048)   // 75776
#define B1_OFF  (LW_OFF + NLAYERS * NMODES * 4) // 79872
#define XS_OFF  (B1_OFF + NMODES * 4)       // 80896
#define W2S_OFF (XS_OFF + MROWS * 4 * 4)    // 81920
#define DEC_OFF (W2S_OFF + NMODES * 4)      // 82944
#define HS_OFF  (DEC_OFF + MROWS * 4 * 4)   // 83968
#define SMEM_TOTAL (HS_OFF + MROWS * 4 * 4) // 84992

__device__ float g_dev[NLAYERS * NMODES];
__device__ __align__(16) uint32_t t2_dev[NLAYERS * 512]; // half2 pair tables
__device__ __align__(16) __half w1sw_dev[NMODES * 64];   // swizzled W1^T image

__device__ __forceinline__ uint32_t smem_u32(const void* p) {
    uint32_t a;
    asm("{ .reg .u64 t; cvta.to.shared.u64 t, %1; cvt.u32.u64 %0, t; }" : "=r"(a) : "l"(p));
    return a;
}

#define CP_ASYNC16(dst, src) \
    asm volatile("cp.async.cg.shared.global [%0], [%1], 16;" :: "r"(dst), "l"(src) : "memory")
#define CP_COMMIT() asm volatile("cp.async.commit_group;" ::: "memory")
#define CP_WAIT0()  asm volatile("cp.async.wait_group 0;" ::: "memory")

#define LDS_B(dst, base, imm) \
    asm volatile("ld.shared.b32 %0, [%1+%2];" : "=r"(dst) : "r"(base), "n"(imm))

__device__ __forceinline__ void mma16(float* c, const uint32_t* a, uint32_t b0, uint32_t b1) {
    asm volatile(
        "mma.sync.aligned.m16n8k16.row.col.f32.f16.f16.f32 "
        "{%0,%1,%2,%3}, {%4,%5,%6,%7}, {%8,%9}, {%0,%1,%2,%3};\n"
        : "+f"(c[0]), "+f"(c[1]), "+f"(c[2]), "+f"(c[3])
        : "r"(a[0]), "r"(a[1]), "r"(a[2]), "r"(a[3]), "r"(b0), "r"(b1));
}

__device__ __forceinline__ void ldsm_x4(uint32_t& r0, uint32_t& r1, uint32_t& r2, uint32_t& r3,
                                        uint32_t addr) {
    asm volatile("ldmatrix.sync.aligned.m8n8.x4.shared.b16 {%0,%1,%2,%3}, [%4];"
                 : "=r"(r0), "=r"(r1), "=r"(r2), "=r"(r3) : "r"(addr));
}

// ---------------- preludes ----------------
__global__ void build_g(const float* __restrict__ fw) {
    int l = blockIdx.x, n = threadIdx.x;
    const float* f = fw + l * 129;
    float acc = f[0] + ((n & 1) ? -f[128] : f[128]);
    float nn = (float)n;
#pragma unroll 4
    for (int k = 1; k < 128; ++k)
        acc += 2.0f * f[k] * cospif((float)k * nn * (1.0f / 128.0f));
    g_dev[l * NMODES + n] = acc * (1.0f / 256.0f);
}

// pair table: t2[l][i] = half2{ g_l[(252-i)&255], g_l[(251-i)&255] }, i<511
__global__ void build_t2() {
    int l = blockIdx.x, i = threadIdx.x + 256 * blockIdx.y;
    if (i >= 512) return;
    uint32_t v = 0;
    if (i < 511) {
        __half lo = __float2half_rn(g_dev[l * NMODES + ((252 - i) & 255)]);
        __half hi = __float2half_rn(g_dev[l * NMODES + ((251 - i) & 255)]);
        __half2 h2 = __halves2half2(lo, hi);
        v = *(const uint32_t*)&h2;
    }
    t2_dev[l * 512 + i] = v;
}

// swizzled W1^T image: element (n, pos*8+jj) <- W1[k=(pos^(n&7))*8+jj][n]
__global__ void build_w1sw(const float* __restrict__ W1) {
    int n = blockIdx.x, j = threadIdx.x;
    int pos = j >> 3, jj = j & 7;
    int k = ((pos ^ (n & 7)) << 3) + jj;
    w1sw_dev[n * 64 + j] = __float2half_rn(W1[k * NMODES + n]);
}

// ---------------- main ----------------
__global__ __launch_bounds__(NTHREADS, 2)
void fno_main(const float* __restrict__ mu, const float* __restrict__ xin,
              const float* __restrict__ b1, const float* __restrict__ lw,
              const float* __restrict__ W2, const float* __restrict__ b2v,
              float* __restrict__ out) {
    extern __shared__ __align__(16) char smem[];
    const uint32_t sb = smem_u32(smem);
    uint32_t* t2s  = (uint32_t*)(smem + T2_OFF);
    float* lw_s    = (float*)(smem + LW_OFF);
    float* b1_s    = (float*)(smem + B1_OFF);
    float* x_s     = (float*)(smem + XS_OFF);
    float* w2_s    = (float*)(smem + W2S_OFF);
    float* dec     = (float*)(smem + DEC_OFF);
    float* hside   = (float*)(smem + HS_OFF);

    const int tid  = threadIdx.x;
    const int lane = tid & 31;
    const int warp = tid >> 5;
    const int lg   = lane >> 2;   // 0..7
    const int tig  = lane & 3;    // 0..3
    const int wm   = warp >> 2;   // 0..1
    const int wn   = warp & 3;    // 0..3
    const size_t row0 = (size_t)blockIdx.x * MROWS;

    // one-shot W1 image copy into h1 region
    {
        const char* src = (const char*)w1sw_dev;
#pragma unroll
        for (int i = 0; i < 8; ++i) {
            int idx = tid + i * NTHREADS;
            CP_ASYNC16(sb + H1_OFF + idx * 16, src + idx * 16);
        }
        CP_COMMIT();
    }

    // tables & small data
    for (int i = tid; i < NLAYERS * 512; i += NTHREADS) t2s[i] = t2_dev[i];
    if (tid < NMODES) b1_s[tid] = b1[tid];
    for (int i = tid; i < NLAYERS * NMODES; i += NTHREADS) lw_s[i] = lw[i];
    for (int i = tid; i < MROWS * 3; i += NTHREADS) {
        int r = i / 3, c = i - r * 3;
        x_s[r * 4 + c] = xin[(row0 + r) * 3 + c];
    }
    if (tid < NMODES) w2_s[tid] = W2[tid];

    // mu -> h0 fp16 words [r][0..31]
    {
        uint32_t* hw0 = (uint32_t*)(smem + H0_OFF);
        for (int i = tid; i < MROWS * 32; i += NTHREADS) {
            int r = i >> 5, w = i & 31;
            float2 v = ((const float2*)(mu + (row0 + r) * 64))[w];
            __half2 h2 = __floats2half2_rn(v.x, v.y);
            hw0[r * HW + w] = *(const uint32_t*)&h2;
        }
    }

    // A ldsm lane row offsets (relative to h buffer base)
    const int a_row = lane & 15;
    const uint32_t a_koff = (uint32_t)((lane >> 4) << 4);
    uint32_t a_rel[2];
#pragma unroll
    for (int mt = 0; mt < 2; ++mt)
        a_rel[mt] = (uint32_t)((wm * 32 + mt * 16 + a_row) * (HW * 4)) + a_koff;

    // W1 (swizzled) ldsm lane offsets (relative to h1 base)
    const int b_nloc = ((lane & 16) >> 1) + (lane & 7);
    const int hi = (lane >> 3) & 1;
    uint32_t w1_off[4];
    int bx[4];
#pragma unroll
    for (int ntp = 0; ntp < 4; ++ntp) {
        int n = wn * 64 + ntp * 16 + b_nloc;
        w1_off[ntp] = (uint32_t)(n << 7);
        bx[ntp] = n & 7;
    }

    // circulant-table per-lane base: addr(ks,nt,b) = rb + 64*ks + (256 - 32*(nt+1-b))
    const uint32_t rb0 = sb + T2_OFF + 1020u + 8u * tig - 4u * lg - 256u * wn - 224u;

    // epilogue special lanes (n in 252..255): wn==3, nt==7, tig>=2
    const bool sp_warp = (wn == 3);
    // epilogue h word index (within a buffer), per (mt,half,nt): computed inline

    float acc[2][8][4];
#define ZERO_ACC()                                   \
    _Pragma("unroll") for (int mt = 0; mt < 2; ++mt) \
    _Pragma("unroll") for (int nt = 0; nt < 8; ++nt) \
    _Pragma("unroll") for (int j = 0; j < 4; ++j) acc[mt][nt][j] = 0.0f;

    CP_WAIT0();
    __syncthreads();

    // ---------------- encoder gemm (A = h0, B = W1 image in h1) -------------
    ZERO_ACC();
    {
        const uint32_t abase = sb + H0_OFF;
        const uint32_t wbase = sb + H1_OFF;
#pragma unroll
        for (int ks = 0; ks < 4; ++ks) {
            uint32_t a[2][4];
            ldsm_x4(a[0][0], a[0][1], a[0][2], a[0][3], abase + a_rel[0] + ks * 32);
            ldsm_x4(a[1][0], a[1][1], a[1][2], a[1][3], abase + a_rel[1] + ks * 32);
            const int seg = ks * 2 + hi;
#pragma unroll
            for (int ntp = 0; ntp < 4; ++ntp) {
                uint32_t b0, b1r, b2, b3;
                ldsm_x4(b0, b1r, b2, b3,
                        wbase + w1_off[ntp] + (uint32_t)(((seg ^ bx[ntp]) & 7) << 4));
                mma16(acc[0][2 * ntp],     a[0], b0, b1r);
                mma16(acc[1][2 * ntp],     a[1], b0, b1r);
                mma16(acc[0][2 * ntp + 1], a[0], b2, b3);
                mma16(acc[1][2 * ntp + 1], a[1], b2, b3);
            }
        }
    }
    __syncthreads();   // all warps done reading W1 before h1 is overwritten

    // encoder epilogue: relu(acc + b1) -> h1; k-cols 253..255 get x, true h -> hside
    {
        uint32_t* hwW = (uint32_t*)(smem + H1_OFF);
#pragma unroll
        for (int mt = 0; mt < 2; ++mt)
#pragma unroll
            for (int half = 0; half < 2; ++half) {
                int r = wm * 32 + mt * 16 + half * 8 + lg;
#pragma unroll
                for (int nt = 0; nt < 8; ++nt) {
                    int n = wn * 64 + nt * 8 + 2 * tig;
                    float2 bv = *(const float2*)(b1_s + n);
                    float v0 = fmaxf(acc[mt][nt][half * 2 + 0] + bv.x, 0.0f);
                    float v1 = fmaxf(acc[mt][nt][half * 2 + 1] + bv.y, 0.0f);
                    if (sp_warp && nt == 7 && tig >= 2) {
                        if (tig == 2) { hside[r * 4 + 0] = v1; v1 = x_s[r * 4 + 0]; }
                        else { hside[r * 4 + 1] = v0; hside[r * 4 + 2] = v1;
                               v0 = x_s[r * 4 + 1]; v1 = x_s[r * 4 + 2]; }
                    }
                    __half2 h2 = __floats2half2_rn(v0, v1);
                    hwW[r * HW + wn * 32 + nt * 4 + tig] = *(const uint32_t*)&h2;
                }
            }
    }
    __syncthreads();

    // ---------------- Fourier stages (h ping-pong, ONE barrier each) --------
    float dsum[4];
#pragma unroll
    for (int s = 0; s < 4; ++s) dsum[s] = 0.0f;

#pragma unroll 1
    for (int l = 1; l <= 4; ++l) {
        const uint32_t rbase = sb + ((l & 1) ? H1_OFF : H0_OFF);   // read buf
        const uint32_t wboff = (l & 1) ? H0_OFF : H1_OFF;          // write buf
        ZERO_ACC();
        uint32_t rb = rb0 + (uint32_t)((l - 1) * 2048);
        uint32_t ra0 = rbase + a_rel[0], ra1 = rbase + a_rel[1];

        // sliding window: v[j] = table[rb + 256 - 32j]; b1[nt]=v[nt], b0[nt]=v[nt+1]
        uint32_t v[9];
        uint32_t a[2][2][4];
        ldsm_x4(a[0][0][0], a[0][0][1], a[0][0][2], a[0][0][3], ra0);
        ldsm_x4(a[0][1][0], a[0][1][1], a[0][1][2], a[0][1][3], ra1);
        LDS_B(v[0], rb, 256); LDS_B(v[1], rb, 224); LDS_B(v[2], rb, 192);
        LDS_B(v[3], rb, 160); LDS_B(v[4], rb, 128); LDS_B(v[5], rb,  96);
        LDS_B(v[6], rb,  64); LDS_B(v[7], rb,  32); LDS_B(v[8], rb,   0);

#pragma unroll
        for (int ks = 0; ks < 16; ++ks) {
            const int cur = ks & 1, nxt = cur ^ 1;
            uint32_t nv0 = 0, nv1 = 0;
            if (ks < 15) {
                ldsm_x4(a[nxt][0][0], a[nxt][0][1], a[nxt][0][2], a[nxt][0][3], ra0 + 32);
                ldsm_x4(a[nxt][1][0], a[nxt][1][1], a[nxt][1][2], a[nxt][1][3], ra1 + 32);
                LDS_B(nv0, rb, 320);   // next slice v[0]
                LDS_B(nv1, rb, 288);   // next slice v[1]
            }
#pragma unroll
            for (int nt = 0; nt < 8; ++nt) {
                mma16(acc[0][nt], a[cur][0], v[nt + 1], v[nt]);
                mma16(acc[1][nt], a[cur][1], v[nt + 1], v[nt]);
            }
            if (ks < 15) {
#pragma unroll
                for (int j = 8; j >= 2; --j) v[j] = v[j - 2];
                v[1] = nv1; v[0] = nv0;
                ra0 += 32; ra1 += 32; rb += 64;
            }
        }

        // epilogue: no barrier needed (reads h_cur own footprint, writes h_next)
        const float* lws = lw_s + (l - 1) * NMODES;
        const bool last = (l == 4);
        uint32_t* hwR = (uint32_t*)(smem + ((l & 1) ? H1_OFF : H0_OFF));
        uint32_t* hwW = (uint32_t*)(smem + wboff);
#pragma unroll
        for (int mt = 0; mt < 2; ++mt)
#pragma unroll
            for (int half = 0; half < 2; ++half) {
                int r = wm * 32 + mt * 16 + half * 8 + lg;
#pragma unroll
                for (int nt = 0; nt < 8; ++nt) {
                    int n = wn * 64 + nt * 8 + 2 * tig;
                    const int widx = r * HW + wn * 32 + nt * 4 + tig;
                    uint32_t hraw = hwR[widx];
                    __half2 ho = *(const __half2*)&hraw;
                    float h0f = __low2float(ho);
                    float h1f = __high2float(ho);
                    const bool sp = sp_warp && nt == 7 && tig >= 2;
                    if (sp) {
                        if (tig == 2) h1f = hside[r * 4 + 0];
                        else { h0f = hside[r * 4 + 1]; h1f = hside[r * 4 + 2]; }
                    }
                    float2 lw2 = *(const float2*)(lws + n);
                    float v0 = fmaxf(acc[mt][nt][half * 2 + 0] + h0f * lw2.x, 0.0f);
                    float v1 = fmaxf(acc[mt][nt][half * 2 + 1] + h1f * lw2.y, 0.0f);
                    if (!last) {
                        if (sp) {
                            if (tig == 2) { hside[r * 4 + 0] = v1; v1 = x_s[r * 4 + 0]; }
                            else { hside[r * 4 + 1] = v0; hside[r * 4 + 2] = v1;
                                   v0 = x_s[r * 4 + 1]; v1 = x_s[r * 4 + 2]; }
                        }
                        __half2 h2 = __floats2half2_rn(v0, v1);
                        hwW[widx] = *(const uint32_t*)&h2;
                    } else {
                        float2 w2v = *(const float2*)(w2_s + n);
                        dsum[mt * 2 + half] += v0 * w2v.x + v1 * w2v.y;
                    }
                }
            }
        __syncthreads();   // h_next visible to all warps (and hside settled)
    }

    // ---------------- decoder reduction ----------------
#pragma unroll
    for (int s = 0; s < 4; ++s) {
        dsum[s] += __shfl_xor_sync(0xffffffffu, dsum[s], 1);
        dsum[s] += __shfl_xor_sync(0xffffffffu, dsum[s], 2);
    }
    if (tig == 0) {
#pragma unroll
        for (int s = 0; s < 4; ++s) {
            int mt = s >> 1, half = s & 1;
            int r = wm * 32 + mt * 16 + half * 8 + lg;
            dec[r * 4 + wn] = dsum[s];
        }
    }
    __syncthreads();
    if (tid < MROWS) {
        const float* d = dec + tid * 4;
        out[row0 + tid] = d[0] + d[1] + d[2] + d[3] + b2v[0];
    }
}

// ---------------------------------------------------------------------------
extern "C" void kernel_launch(void* const* d_in, const int* in_sizes, int n_in,
                              void* d_out, int out_size) {
    const float* mu = (const float*)d_in[0];
    const float* x  = (const float*)d_in[1];
    const float* W1 = (const float*)d_in[2];
    const float* b1 = (const float*)d_in[3];
    const float* fw = (const float*)d_in[4];
    const float* lw = (const float*)d_in[5];
    const float* W2 = (const float*)d_in[6];
    const float* b2 = (const float*)d_in[7];
    float* out = (float*)d_out;

    const int B = in_sizes[0] / 64;
    const int nblocks = B / MROWS;

    build_g<<<NLAYERS, NMODES>>>(fw);
    build_t2<<<dim3(NLAYERS, 2), 256>>>();
    build_w1sw<<<NMODES, 64>>>(W1);

    cudaFuncSetAttribute(fno_main, cudaFuncAttributeMaxDynamicSharedMemorySize, SMEM_TOTAL);
    fno_main<<<nblocks, NTHREADS, SMEM_TOTAL>>>(mu, x, b1, lw, W2, b2, out);
}

// round 13
// speedup vs baseline: 1.0398x; 1.0398x over previous
#include <cuda_runtime.h>
#include <cuda_fp16.h>
#include <cstdint>

// ---------------------------------------------------------------------------
// FNO on sm_103a. Circulant Fourier layers via a 2KB reversed-g pair table:
// B[k][n] = g[(n-k-3) mod 256]. Uncropped circulant rows k=253..255 ARE the
// x-term coefficients, so x0..x2 live in h's k-columns 253..255 and the MMA
// computes conv + x-term together. True h[253..255] in a 1KB side array.
//   h0 = relu(mu @ W1 + b1)           (W1 via one-shot cp.async, ldsm path)
//   h  = relu(circ_g([h|x]) + h*lw)   l=0..3
//   out = h @ W2 + b2                 (fused into stage-4 epilogue, fp32)
// R13 = R11 + named group barriers: warps with wm=0 / wm=1 touch disjoint h
// rows, so they sync via bar.sync(wm+1,128) instead of __syncthreads —
// groups stay internally lockstep (LDS broadcast) but decouple across.
// 256 threads, 64 rows/CTA, 82KB SMEM -> 2 CTAs/SM. No weight streaming.
// ---------------------------------------------------------------------------

#define NMODES 256
#define NLAYERS 4
#define MROWS 64
#define NTHREADS 256
#define HW 132                              // h row stride in 32-bit words
#define H_BYTES (MROWS * HW * 4)            // 33792
#define W1_OFF  H_BYTES                     // 32KB swizzled W1 image
#define T2_OFF  (W1_OFF + 32768)            // 66560: 4 x 2048B pair tables
#define B1_OFF  (T2_OFF + NLAYERS * 2048)   // 74752: b1 (fp32)
#define LW_OFF  (B1_OFF + NMODES * 4)       // 75776: 4x lw (fp32)
#define XS_OFF  (LW_OFF + NLAYERS * NMODES * 4) // 79872
#define W2S_OFF (XS_OFF + MROWS * 4 * 4)    // 80896
#define DEC_OFF (W2S_OFF + NMODES * 4)      // 81920
#define HS_OFF  (DEC_OFF + MROWS * 4 * 4)   // 82944: h[253..255] side (fp32)
#define SMEM_TOTAL (HS_OFF + MROWS * 4 * 4) // 83968

__device__ float g_dev[NLAYERS * NMODES];
__device__ __align__(16) uint32_t t2_dev[NLAYERS * 512]; // half2 pair tables
__device__ __align__(16) __half w1sw_dev[NMODES * 64];   // swizzled W1^T image

__device__ __forceinline__ uint32_t smem_u32(const void* p) {
    uint32_t a;
    asm("{ .reg .u64 t; cvta.to.shared.u64 t, %1; cvt.u32.u64 %0, t; }" : "=r"(a) : "l"(p));
    return a;
}

#define CP_ASYNC16(dst, src) \
    asm volatile("cp.async.cg.shared.global [%0], [%1], 16;" :: "r"(dst), "l"(src) : "memory")
#define CP_COMMIT() asm volatile("cp.async.commit_group;" ::: "memory")
#define CP_WAIT0()  asm volatile("cp.async.wait_group 0;" ::: "memory")

#define LDS_B(dst, base, imm) \
    asm volatile("ld.shared.b32 %0, [%1+%2];" : "=r"(dst) : "r"(base), "n"(imm))

// group barrier: warps 0-3 (wm=0) use barrier 1, warps 4-7 (wm=1) barrier 2
#define BAR_GROUP() \
    asm volatile("bar.sync %0, 128;" :: "r"(wm + 1) : "memory")

__device__ __forceinline__ void mma16(float* c, const uint32_t* a, uint32_t b0, uint32_t b1) {
    asm volatile(
        "mma.sync.aligned.m16n8k16.row.col.f32.f16.f16.f32 "
        "{%0,%1,%2,%3}, {%4,%5,%6,%7}, {%8,%9}, {%0,%1,%2,%3};\n"
        : "+f"(c[0]), "+f"(c[1]), "+f"(c[2]), "+f"(c[3])
        : "r"(a[0]), "r"(a[1]), "r"(a[2]), "r"(a[3]), "r"(b0), "r"(b1));
}

__device__ __forceinline__ void ldsm_x4(uint32_t& r0, uint32_t& r1, uint32_t& r2, uint32_t& r3,
                                        uint32_t addr) {
    asm volatile("ldmatrix.sync.aligned.m8n8.x4.shared.b16 {%0,%1,%2,%3}, [%4];"
                 : "=r"(r0), "=r"(r1), "=r"(r2), "=r"(r3) : "r"(addr));
}

// ---------------- preludes ----------------
__global__ void build_g(const float* __restrict__ fw) {
    int l = blockIdx.x, n = threadIdx.x;
    const float* f = fw + l * 129;
    float acc = f[0] + ((n & 1) ? -f[128] : f[128]);
    float nn = (float)n;
#pragma unroll 4
    for (int k = 1; k < 128; ++k)
        acc += 2.0f * f[k] * cospif((float)k * nn * (1.0f / 128.0f));
    g_dev[l * NMODES + n] = acc * (1.0f / 256.0f);
}

// pair table: t2[l][i] = half2{ g_l[(252-i)&255], g_l[(251-i)&255] }, i<511
__global__ void build_t2() {
    int l = blockIdx.x, i = threadIdx.x + 256 * blockIdx.y;
    if (i >= 512) return;
    uint32_t v = 0;
    if (i < 511) {
        __half lo = __float2half_rn(g_dev[l * NMODES + ((252 - i) & 255)]);
        __half hi = __float2half_rn(g_dev[l * NMODES + ((251 - i) & 255)]);
        __half2 h2 = __halves2half2(lo, hi);
        v = *(const uint32_t*)&h2;
    }
    t2_dev[l * 512 + i] = v;
}

// swizzled W1^T image: element (n, pos*8+jj) <- W1[k=(pos^(n&7))*8+jj][n]
__global__ void build_w1sw(const float* __restrict__ W1) {
    int n = blockIdx.x, j = threadIdx.x;
    int pos = j >> 3, jj = j & 7;
    int k = ((pos ^ (n & 7)) << 3) + jj;
    w1sw_dev[n * 64 + j] = __float2half_rn(W1[k * NMODES + n]);
}

// ---------------- main ----------------
__global__ __launch_bounds__(NTHREADS, 2)
void fno_main(const float* __restrict__ mu, const float* __restrict__ xin,
              const float* __restrict__ b1, const float* __restrict__ lw,
              const float* __restrict__ W2, const float* __restrict__ b2v,
              float* __restrict__ out) {
    extern __shared__ __align__(16) char smem[];
    const uint32_t sb = smem_u32(smem);
    uint32_t* hw   = (uint32_t*)smem;
    uint32_t* t2s  = (uint32_t*)(smem + T2_OFF);
    float* b1_s    = (float*)(smem + B1_OFF);
    float* lw_s    = (float*)(smem + LW_OFF);
    float* x_s     = (float*)(smem + XS_OFF);
    float* w2_s    = (float*)(smem + W2S_OFF);
    float* dec     = (float*)(smem + DEC_OFF);
    float* hside   = (float*)(smem + HS_OFF);

    const int tid  = threadIdx.x;
    const int lane = tid & 31;
    const int warp = tid >> 5;
    const int lg   = lane >> 2;   // 0..7
    const int tig  = lane & 3;    // 0..3
    const int wm   = warp >> 2;   // 0..1
    const int wn   = warp & 3;    // 0..3
    const size_t row0 = (size_t)blockIdx.x * MROWS;

    // one-shot W1 image copy
    {
        const char* src = (const char*)w1sw_dev;
#pragma unroll
        for (int i = 0; i < 8; ++i) {
            int idx = tid + i * NTHREADS;
            CP_ASYNC16(sb + W1_OFF + idx * 16, src + idx * 16);
        }
        CP_COMMIT();
    }

    // tables & small data
    for (int i = tid; i < NLAYERS * 512; i += NTHREADS) t2s[i] = t2_dev[i];
    if (tid < NMODES) b1_s[tid] = b1[tid];
    for (int i = tid; i < NLAYERS * NMODES; i += NTHREADS) lw_s[i] = lw[i];
    for (int i = tid; i < MROWS * 3; i += NTHREADS) {
        int r = i / 3, c = i - r * 3;
        x_s[r * 4 + c] = xin[(row0 + r) * 3 + c];
    }
    if (tid < NMODES) w2_s[tid] = W2[tid];

    // mu -> h fp16 words [r][0..31]
    for (int i = tid; i < MROWS * 32; i += NTHREADS) {
        int r = i >> 5, w = i & 31;
        float2 v = ((const float2*)(mu + (row0 + r) * 64))[w];
        __half2 h2 = __floats2half2_rn(v.x, v.y);
        hw[r * HW + w] = *(const uint32_t*)&h2;
    }

    // A ldsm lane bases
    const int a_row = lane & 15;
    const uint32_t a_koff = (uint32_t)((lane >> 4) << 4);
    uint32_t a_base[2];
#pragma unroll
    for (int mt = 0; mt < 2; ++mt)
        a_base[mt] = sb + (wm * 32 + mt * 16 + a_row) * (HW * 4) + a_koff;

    // W1 (swizzled) ldsm lane bases
    const int b_nloc = ((lane & 16) >> 1) + (lane & 7);
    const int hi = (lane >> 3) & 1;
    uint32_t w1_off[4];
    int bx[4];
#pragma unroll
    for (int ntp = 0; ntp < 4; ++ntp) {
        int n = wn * 64 + ntp * 16 + b_nloc;
        w1_off[ntp] = (uint32_t)(n << 7);
        bx[ntp] = n & 7;
    }

    // circulant-table per-lane base: addr(ks,nt,b) = rb + 64*ks + (256 - 32*(nt+1-b))
    const uint32_t rb0 = sb + T2_OFF + 1020u + 8u * tig - 4u * lg - 256u * wn - 224u;

    // epilogue special lanes (n in 252..255): wn==3, nt==7, tig>=2
    const bool sp_warp = (wn == 3);

    float acc[2][8][4];
#define ZERO_ACC()                                   \
    _Pragma("unroll") for (int mt = 0; mt < 2; ++mt) \
    _Pragma("unroll") for (int nt = 0; nt < 8; ++nt) \
    _Pragma("unroll") for (int j = 0; j < 4; ++j) acc[mt][nt][j] = 0.0f;

    CP_WAIT0();
    __syncthreads();   // full: W1 image + tables + h0 visible to everyone

    // ---------------- encoder gemm (K=64, W1 image via ldsm) ----------------
    ZERO_ACC();
    {
        const uint32_t wbase = sb + W1_OFF;
#pragma unroll
        for (int ks = 0; ks < 4; ++ks) {
            uint32_t a[2][4];
            ldsm_x4(a[0][0], a[0][1], a[0][2], a[0][3], a_base[0] + ks * 32);
            ldsm_x4(a[1][0], a[1][1], a[1][2], a[1][3], a_base[1] + ks * 32);
            const int seg = ks * 2 + hi;
#pragma unroll
            for (int ntp = 0; ntp < 4; ++ntp) {
                uint32_t b0, b1r, b2, b3;
                ldsm_x4(b0, b1r, b2, b3,
                        wbase + w1_off[ntp] + (uint32_t)(((seg ^ bx[ntp]) & 7) << 4));
                mma16(acc[0][2 * ntp],     a[0], b0, b1r);
                mma16(acc[1][2 * ntp],     a[1], b0, b1r);
                mma16(acc[0][2 * ntp + 1], a[0], b2, b3);
                mma16(acc[1][2 * ntp + 1], a[1], b2, b3);
            }
        }
    }
    BAR_GROUP();   // group's h rows fully read by group's warps
    // encoder epilogue: relu(acc + b1) -> h; k-cols 253..255 get x, true h -> hside
#pragma unroll
    for (int mt = 0; mt < 2; ++mt)
#pragma unroll
        for (int half = 0; half < 2; ++half) {
            int r = wm * 32 + mt * 16 + half * 8 + lg;
#pragma unroll
            for (int nt = 0; nt < 8; ++nt) {
                int n = wn * 64 + nt * 8 + 2 * tig;
                float2 bv = *(const float2*)(b1_s + n);
                float v0 = fmaxf(acc[mt][nt][half * 2 + 0] + bv.x, 0.0f);
                float v1 = fmaxf(acc[mt][nt][half * 2 + 1] + bv.y, 0.0f);
                if (sp_warp && nt == 7 && tig >= 2) {
                    if (tig == 2) { hside[r * 4 + 0] = v1; v1 = x_s[r * 4 + 0]; }
                    else { hside[r * 4 + 1] = v0; hside[r * 4 + 2] = v1;
                           v0 = x_s[r * 4 + 1]; v1 = x_s[r * 4 + 2]; }
                }
                __half2 h2 = __floats2half2_rn(v0, v1);
                hw[r * HW + wn * 32 + nt * 4 + tig] = *(const uint32_t*)&h2;
            }
        }
    BAR_GROUP();   // group's new h visible within group

    // ---------------- Fourier stages ----------------
    float dsum[4];
#pragma unroll
    for (int s = 0; s < 4; ++s) dsum[s] = 0.0f;

#pragma unroll 1
    for (int l = 1; l <= 4; ++l) {
        ZERO_ACC();
        uint32_t rb = rb0 + (uint32_t)((l - 1) * 2048);
        uint32_t ra0 = a_base[0], ra1 = a_base[1];

        // sliding window: v[j] = table[rb + 256 - 32j]; b1[nt]=v[nt], b0[nt]=v[nt+1]
        uint32_t v[9];
        uint32_t a[2][2][4];
        ldsm_x4(a[0][0][0], a[0][0][1], a[0][0][2], a[0][0][3], ra0);
        ldsm_x4(a[0][1][0], a[0][1][1], a[0][1][2], a[0][1][3], ra1);
        LDS_B(v[0], rb, 256); LDS_B(v[1], rb, 224); LDS_B(v[2], rb, 192);
        LDS_B(v[3], rb, 160); LDS_B(v[4], rb, 128); LDS_B(v[5], rb,  96);
        LDS_B(v[6], rb,  64); LDS_B(v[7], rb,  32); LDS_B(v[8], rb,   0);

#pragma unroll
        for (int ks = 0; ks < 16; ++ks) {
            const int cur = ks & 1, nxt = cur ^ 1;
            uint32_t nv0 = 0, nv1 = 0;
            if (ks < 15) {
                ldsm_x4(a[nxt][0][0], a[nxt][0][1], a[nxt][0][2], a[nxt][0][3], ra0 + 32);
                ldsm_x4(a[nxt][1][0], a[nxt][1][1], a[nxt][1][2], a[nxt][1][3], ra1 + 32);
                LDS_B(nv0, rb, 320);   // next slice v[0]
                LDS_B(nv1, rb, 288);   // next slice v[1]
            }
#pragma unroll
            for (int nt = 0; nt < 8; ++nt) {
                mma16(acc[0][nt], a[cur][0], v[nt + 1], v[nt]);
                mma16(acc[1][nt], a[cur][1], v[nt + 1], v[nt]);
            }
            if (ks < 15) {
#pragma unroll
                for (int j = 8; j >= 2; --j) v[j] = v[j - 2];
                v[1] = nv1; v[0] = nv0;
                ra0 += 32; ra1 += 32; rb += 64;
            }
        }

        BAR_GROUP();   // group's h rows fully read

        const float* lws = lw_s + (l - 1) * NMODES;
        const bool last = (l == 4);
#pragma unroll
        for (int mt = 0; mt < 2; ++mt)
#pragma unroll
            for (int half = 0; half < 2; ++half) {
                int r = wm * 32 + mt * 16 + half * 8 + lg;
#pragma unroll
                for (int nt = 0; nt < 8; ++nt) {
                    int n = wn * 64 + nt * 8 + 2 * tig;
                    const int widx = r * HW + wn * 32 + nt * 4 + tig;
                    uint32_t hraw = hw[widx];
                    __half2 ho = *(const __half2*)&hraw;
                    float h0f = __low2float(ho);
                    float h1f = __high2float(ho);
                    const bool sp = sp_warp && nt == 7 && tig >= 2;
                    if (sp) {
                        if (tig == 2) h1f = hside[r * 4 + 0];
                        else { h0f = hside[r * 4 + 1]; h1f = hside[r * 4 + 2]; }
                    }
                    float2 lw2 = *(const float2*)(lws + n);
                    float v0 = fmaxf(acc[mt][nt][half * 2 + 0] + h0f * lw2.x, 0.0f);
                    float v1 = fmaxf(acc[mt][nt][half * 2 + 1] + h1f * lw2.y, 0.0f);
                    if (!last) {
                        if (sp) {
                            if (tig == 2) { hside[r * 4 + 0] = v1; v1 = x_s[r * 4 + 0]; }
                            else { hside[r * 4 + 1] = v0; hside[r * 4 + 2] = v1;
                                   v0 = x_s[r * 4 + 1]; v1 = x_s[r * 4 + 2]; }
                        }
                        __half2 h2 = __floats2half2_rn(v0, v1);
                        hw[widx] = *(const uint32_t*)&h2;
                    } else {
                        float2 w2v = *(const float2*)(w2_s + n);
                        dsum[mt * 2 + half] += v0 * w2v.x + v1 * w2v.y;
                    }
                }
            }
        if (!last) BAR_GROUP();   // group's new h visible within group
    }

    // ---------------- decoder reduction ----------------
#pragma unroll
    for (int s = 0; s < 4; ++s) {
        dsum[s] += __shfl_xor_sync(0xffffffffu, dsum[s], 1);
        dsum[s] += __shfl_xor_sync(0xffffffffu, dsum[s], 2);
    }
    if (tig == 0) {
#pragma unroll
        for (int s = 0; s < 4; ++s) {
            int mt = s >> 1, half = s & 1;
            int r = wm * 32 + mt * 16 + half * 8 + lg;
            dec[r * 4 + wn] = dsum[s];
        }
    }
    __syncthreads();   // full: dec written by all warps before cross-warp read
    if (tid < MROWS) {
        const float* d = dec + tid * 4;
        out[row0 + tid] = d[0] + d[1] + d[2] + d[3] + b2v[0];
    }
}

// ---------------------------------------------------------------------------
extern "C" void kernel_launch(void* const* d_in, const int* in_sizes, int n_in,
                              void* d_out, int out_size) {
    const float* mu = (const float*)d_in[0];
    const float* x  = (const float*)d_in[1];
    const float* W1 = (const float*)d_in[2];
    const float* b1 = (const float*)d_in[3];
    const float* fw = (const float*)d_in[4];
    const float* lw = (const float*)d_in[5];
    const float* W2 = (const float*)d_in[6];
    const float* b2 = (const float*)d_in[7];
    float* out = (float*)d_out;

    const int B = in_sizes[0] / 64;
    const int nblocks = B / MROWS;

    build_g<<<NLAYERS, NMODES>>>(fw);
    build_t2<<<dim3(NLAYERS, 2), 256>>>();
    build_w1sw<<<NMODES, 64>>>(W1);

    cudaFuncSetAttribute(fno_main, cudaFuncAttributeMaxDynamicSharedMemorySize, SMEM_TOTAL);
    fno_main<<<nblocks, NTHREADS, SMEM_TOTAL>>>(mu, x, b1, lw, W2, b2, out);
}